// round 1
// baseline (speedup 1.0000x reference)
#include <cuda_runtime.h>
#include <cuda_bf16.h>

// Problem constants
#define NB 4
#define NC 64
#define NH 128
#define NW 128
#define NN 16
#define NPIX (NB*NH*NW)   // 65536 pixels

// Scratch (allocation-free rule: __device__ globals)
static __device__ float g_W96[96*64];                 // rows 0..63: M = dtw@xw[:4]; 64..79: B rows; 80..95: C rows
static __device__ float g_A2[64*16];                  // -exp(A_log)*log2(e)
static __device__ float g_delta[(size_t)NPIX*64];     // [p][c]
static __device__ float g_u[(size_t)NPIX*64];         // [p][c]  (x transposed)
static __device__ float g_Bc[(size_t)NPIX*16];        // [p][n]
static __device__ float g_Cc[(size_t)NPIX*16];        // [p][n]
static __device__ float g_yh[(size_t)NPIX*64];        // [p][c]
static __device__ float g_yv[(size_t)NPIX*64];        // [p][c]

__device__ __forceinline__ float fexp2(float x) {
    float r;
    asm("ex2.approx.f32 %0, %1;" : "=f"(r) : "f"(x));
    return r;
}

// ---------------------------------------------------------------------------
// Setup: fold dt projection into a single [64,64] matrix M, copy B/C weight
// rows, and pre-scale A = -exp(A_log) by log2(e) so the scan uses ex2 directly.
// ---------------------------------------------------------------------------
__global__ void setup_kernel(const float* __restrict__ A_log,
                             const float* __restrict__ xw,    // [36,64]
                             const float* __restrict__ dtw)   // [64,4]
{
    int i = blockIdx.x * blockDim.x + threadIdx.x;
    if (i < 96*64) {
        int r = i >> 6, c = i & 63;
        float v;
        if (r < 64) {
            v = dtw[r*4+0]*xw[0*64+c] + dtw[r*4+1]*xw[1*64+c]
              + dtw[r*4+2]*xw[2*64+c] + dtw[r*4+3]*xw[3*64+c];
        } else {
            v = xw[(r - 64 + 4)*64 + c];
        }
        g_W96[i] = v;
    }
    if (i < 64*16) {
        g_A2[i] = -__expf(A_log[i]) * 1.4426950408889634f;
    }
}

// ---------------------------------------------------------------------------
// Projection: one block per (b,h) row of 128 pixels; thread = pixel (w).
// u[64] lives in registers (coalesced global loads). Weights broadcast from
// smem via LDS.128. Outputs staged through a padded smem tile so all global
// writes are >=64B-contiguous segments.
// ---------------------------------------------------------------------------
__global__ __launch_bounds__(128) void proj_kernel(const float* __restrict__ x,
                                                   const float* __restrict__ dtb)
{
    __shared__ __align__(16) float s_w[96*64];   // 24 KB
    __shared__ float s_tile[128*17];             // padded: stride 17 kills conflicts
    __shared__ float s_bias[64];

    int bh = blockIdx.x;          // 0..511
    int b  = bh >> 7;
    int h  = bh & 127;
    int w  = threadIdx.x;

    for (int i = threadIdx.x; i < 96*64; i += 128) s_w[i] = g_W96[i];
    if (threadIdx.x < 64) s_bias[threadIdx.x] = dtb[threadIdx.x];

    // Load this pixel's channel vector: x[b, c, h, w]
    float u[64];
    const float* xp = x + ((size_t)(b*64)*128 + h)*128 + w;
    #pragma unroll
    for (int c = 0; c < 64; c++) u[c] = xp[(size_t)c*16384];

    __syncthreads();

    size_t pbase = (size_t)bh * 128;   // pixel index of (b,h,w=0)

    // 6 compute chunks of 16 outputs: 0..3 delta_pre, 4 = Bc, 5 = Cc
    for (int chunk = 0; chunk < 6; chunk++) {
        int o0 = chunk * 16;
        #pragma unroll 4
        for (int j = 0; j < 16; j++) {
            const float4* wr = (const float4*)(s_w + (o0 + j)*64);
            float acc = 0.f;
            #pragma unroll
            for (int c4 = 0; c4 < 16; c4++) {
                float4 wv = wr[c4];   // uniform -> smem broadcast
                acc += u[4*c4+0]*wv.x + u[4*c4+1]*wv.y
                     + u[4*c4+2]*wv.z + u[4*c4+3]*wv.w;
            }
            s_tile[w*17 + j] = acc;
        }
        __syncthreads();
        #pragma unroll
        for (int it = 0; it < 16; it++) {
            int idx = it*128 + threadIdx.x;   // 0..2047
            int pix = idx >> 4;
            int j   = idx & 15;
            float v = s_tile[pix*17 + j];
            if (chunk < 4) {
                int o = chunk*16 + j;
                v += s_bias[o];
                v = (v > 15.f) ? v : log1pf(__expf(v));   // softplus
                g_delta[(pbase + pix)*64 + o] = v;
            } else if (chunk == 4) {
                g_Bc[(pbase + pix)*16 + j] = v;
            } else {
                g_Cc[(pbase + pix)*16 + j] = v;
            }
        }
        __syncthreads();
    }

    // Write u transposed to [p][c] through the same staging path (coalesced)
    #pragma unroll
    for (int cc = 0; cc < 4; cc++) {
        #pragma unroll
        for (int j = 0; j < 16; j++) s_tile[w*17 + j] = u[cc*16 + j];
        __syncthreads();
        #pragma unroll
        for (int it = 0; it < 16; it++) {
            int idx = it*128 + threadIdx.x;
            int pix = idx >> 4;
            int j   = idx & 15;
            g_u[(pbase + pix)*64 + cc*16 + j] = s_tile[pix*17 + j];
        }
        __syncthreads();
    }
}

// ---------------------------------------------------------------------------
// Scan: blocks 0..255 handle horizontal sequences (2 per block), 256..511
// vertical. Thread = (sequence, channel d); 16 SSM states + A row + B/C
// coefficients in registers. All global accesses are 256B-contiguous per
// 64-thread channel group.
// ---------------------------------------------------------------------------
__global__ __launch_bounds__(128) void scan_kernel()
{
    int g  = threadIdx.x >> 6;     // sub-sequence within block
    int d  = threadIdx.x & 63;     // channel
    int blk = blockIdx.x;          // 0..511
    int dir = blk >> 8;            // 0 = H, 1 = V
    int s   = ((blk & 255) << 1) | g;   // 0..511
    int b   = s >> 7;
    int rc  = s & 127;             // h for H-scan, w for V-scan

    size_t pix0;
    int stride;
    float* __restrict__ yout;
    if (dir == 0) { pix0 = ((size_t)(b*128 + rc))*128; stride = 1;   yout = g_yh; }
    else          { pix0 = (size_t)b*16384 + rc;       stride = 128; yout = g_yv; }

    float A2r[16];
    #pragma unroll
    for (int n = 0; n < 16; n++) A2r[n] = g_A2[d*16 + n];

    float hs[16];
    #pragma unroll
    for (int n = 0; n < 16; n++) hs[n] = 0.f;

    size_t p = pix0;
    for (int l = 0; l < 128; l++, p += stride) {
        float delta = g_delta[p*64 + d];
        float uu    = g_u[p*64 + d];
        const float4* Bp = (const float4*)(g_Bc + p*16);
        const float4* Cp = (const float4*)(g_Cc + p*16);
        float4 B0 = Bp[0], B1 = Bp[1], B2 = Bp[2], B3 = Bp[3];
        float4 C0 = Cp[0], C1 = Cp[1], C2 = Cp[2], C3 = Cp[3];
        float du = delta * uu;
        float y = 0.f;

#define SSM_STEP(n, bv, cv)                                   \
        {                                                     \
            float dA = fexp2(delta * A2r[n]);                 \
            hs[n] = fmaf(dA, hs[n], du * (bv));               \
            y = fmaf(hs[n], (cv), y);                         \
        }
        SSM_STEP(0,  B0.x, C0.x); SSM_STEP(1,  B0.y, C0.y);
        SSM_STEP(2,  B0.z, C0.z); SSM_STEP(3,  B0.w, C0.w);
        SSM_STEP(4,  B1.x, C1.x); SSM_STEP(5,  B1.y, C1.y);
        SSM_STEP(6,  B1.z, C1.z); SSM_STEP(7,  B1.w, C1.w);
        SSM_STEP(8,  B2.x, C2.x); SSM_STEP(9,  B2.y, C2.y);
        SSM_STEP(10, B2.z, C2.z); SSM_STEP(11, B2.w, C2.w);
        SSM_STEP(12, B3.x, C3.x); SSM_STEP(13, B3.y, C3.y);
        SSM_STEP(14, B3.z, C3.z); SSM_STEP(15, B3.w, C3.w);
#undef SSM_STEP

        yout[p*64 + d] = y;
    }
}

// ---------------------------------------------------------------------------
// Combine + transpose: out[b,c,h,w] = yh[p][c] + yv[p][c] + 2*D[c]*x[b,c,h,w]
// 32x32 smem tile per (c-tile, w-tile) so both sides are coalesced.
// ---------------------------------------------------------------------------
__global__ void combine_kernel(const float* __restrict__ x,
                               const float* __restrict__ Dv,
                               float* __restrict__ out)
{
    __shared__ float s[32][33];
    int t    = blockIdx.x;
    int tile = t & 7;          // 2 c-tiles x 4 w-tiles
    int bh   = t >> 3;
    int b    = bh >> 7;
    int h    = bh & 127;
    int c0   = (tile & 1) * 32;
    int w0   = (tile >> 1) * 32;
    int tx   = threadIdx.x;    // 0..31
    int ty   = threadIdx.y;    // 0..7
    size_t pbase = (size_t)bh * 128;

    #pragma unroll
    for (int i = 0; i < 4; i++) {
        int wi = ty + i*8;
        size_t idx = (pbase + w0 + wi)*64 + c0 + tx;
        s[wi][tx] = g_yh[idx] + g_yv[idx];
    }
    __syncthreads();
    #pragma unroll
    for (int i = 0; i < 4; i++) {
        int ci = ty + i*8;
        int c  = c0 + ci;
        size_t xi = (((size_t)(b*64 + c))*128 + h)*128 + w0 + tx;
        out[xi] = s[tx][ci] + 2.f * Dv[c] * x[xi];
    }
}

// ---------------------------------------------------------------------------
extern "C" void kernel_launch(void* const* d_in, const int* in_sizes, int n_in,
                              void* d_out, int out_size)
{
    const float* x     = (const float*)d_in[0];   // [4,64,128,128]
    const float* A_log = (const float*)d_in[1];   // [64,16]
    const float* Dv    = (const float*)d_in[2];   // [64]
    const float* xw    = (const float*)d_in[3];   // [36,64]
    const float* dtw   = (const float*)d_in[4];   // [64,4]
    const float* dtb   = (const float*)d_in[5];   // [64]
    float* out = (float*)d_out;

    setup_kernel<<<24, 256>>>(A_log, xw, dtw);
    proj_kernel<<<NB*NH, 128>>>(x, dtb);
    scan_kernel<<<512, 128>>>();
    combine_kernel<<<NB*NH*8, dim3(32, 8)>>>(x, Dv, out);
}

// round 2
// speedup vs baseline: 1.2785x; 1.2785x over previous
#include <cuda_runtime.h>
#include <cuda_bf16.h>

// Problem constants
#define NB 4
#define NC 64
#define NH 128
#define NW 128
#define NN 16
#define NPIX (NB*NH*NW)   // 65536 pixels

// Scratch (allocation-free rule: __device__ globals)
static __device__ float g_W96[96*64];                 // rows 0..63: M = dtw@xw[:4]; 64..79: B rows; 80..95: C rows
static __device__ float g_A2[64*16];                  // -exp(A_log)*log2(e)
static __device__ float g_delta[(size_t)NPIX*64];     // [p][c]
static __device__ float g_u[(size_t)NPIX*64];         // [p][c]  (x transposed)
static __device__ float g_Bc[(size_t)NPIX*16];        // [p][n]
static __device__ float g_Cc[(size_t)NPIX*16];        // [p][n]
static __device__ float g_yh[(size_t)NPIX*64];        // [p][c]
static __device__ float g_yv[(size_t)NPIX*64];        // [p][c]

__device__ __forceinline__ float fexp2(float x) {
    float r;
    asm("ex2.approx.f32 %0, %1;" : "=f"(r) : "f"(x));
    return r;
}

// ---------------------------------------------------------------------------
// Setup: fold dt projection into a single [64,64] matrix M, copy B/C weight
// rows, and pre-scale A = -exp(A_log) by log2(e) so the scan uses ex2 directly.
// ---------------------------------------------------------------------------
__global__ void setup_kernel(const float* __restrict__ A_log,
                             const float* __restrict__ xw,    // [36,64]
                             const float* __restrict__ dtw)   // [64,4]
{
    int i = blockIdx.x * blockDim.x + threadIdx.x;
    if (i < 96*64) {
        int r = i >> 6, c = i & 63;
        float v;
        if (r < 64) {
            v = dtw[r*4+0]*xw[0*64+c] + dtw[r*4+1]*xw[1*64+c]
              + dtw[r*4+2]*xw[2*64+c] + dtw[r*4+3]*xw[3*64+c];
        } else {
            v = xw[(r - 64 + 4)*64 + c];
        }
        g_W96[i] = v;
    }
    if (i < 64*16) {
        g_A2[i] = -__expf(A_log[i]) * 1.4426950408889634f;
    }
}

// ---------------------------------------------------------------------------
// Projection: one block per (b,h) row of 128 pixels; thread = pixel (w).
// u[64] lives in registers (coalesced global loads). Weights broadcast from
// smem via LDS.128. Outputs staged through a padded smem tile so all global
// writes are >=64B-contiguous segments.
// ---------------------------------------------------------------------------
__global__ __launch_bounds__(128) void proj_kernel(const float* __restrict__ x,
                                                   const float* __restrict__ dtb)
{
    __shared__ __align__(16) float s_w[96*64];   // 24 KB
    __shared__ float s_tile[128*17];             // padded: stride 17 kills conflicts
    __shared__ float s_bias[64];

    int bh = blockIdx.x;          // 0..511
    int b  = bh >> 7;
    int h  = bh & 127;
    int w  = threadIdx.x;

    for (int i = threadIdx.x; i < 96*64; i += 128) s_w[i] = g_W96[i];
    if (threadIdx.x < 64) s_bias[threadIdx.x] = dtb[threadIdx.x];

    // Load this pixel's channel vector: x[b, c, h, w]
    float u[64];
    const float* xp = x + ((size_t)(b*64)*128 + h)*128 + w;
    #pragma unroll
    for (int c = 0; c < 64; c++) u[c] = xp[(size_t)c*16384];

    __syncthreads();

    size_t pbase = (size_t)bh * 128;   // pixel index of (b,h,w=0)

    // 6 compute chunks of 16 outputs: 0..3 delta_pre, 4 = Bc, 5 = Cc
    for (int chunk = 0; chunk < 6; chunk++) {
        int o0 = chunk * 16;
        #pragma unroll 4
        for (int j = 0; j < 16; j++) {
            const float4* wr = (const float4*)(s_w + (o0 + j)*64);
            float acc = 0.f;
            #pragma unroll
            for (int c4 = 0; c4 < 16; c4++) {
                float4 wv = wr[c4];   // uniform -> smem broadcast
                acc += u[4*c4+0]*wv.x + u[4*c4+1]*wv.y
                     + u[4*c4+2]*wv.z + u[4*c4+3]*wv.w;
            }
            s_tile[w*17 + j] = acc;
        }
        __syncthreads();
        #pragma unroll
        for (int it = 0; it < 16; it++) {
            int idx = it*128 + threadIdx.x;   // 0..2047
            int pix = idx >> 4;
            int j   = idx & 15;
            float v = s_tile[pix*17 + j];
            if (chunk < 4) {
                int o = chunk*16 + j;
                v += s_bias[o];
                // softplus via MUFU fast-math (ex2 + lg2), clamp large inputs
                v = (v > 15.f) ? v : __logf(1.f + __expf(v));
                g_delta[(pbase + pix)*64 + o] = v;
            } else if (chunk == 4) {
                g_Bc[(pbase + pix)*16 + j] = v;
            } else {
                g_Cc[(pbase + pix)*16 + j] = v;
            }
        }
        __syncthreads();
    }

    // Write u transposed to [p][c] through the same staging path (coalesced)
    #pragma unroll
    for (int cc = 0; cc < 4; cc++) {
        #pragma unroll
        for (int j = 0; j < 16; j++) s_tile[w*17 + j] = u[cc*16 + j];
        __syncthreads();
        #pragma unroll
        for (int it = 0; it < 16; it++) {
            int idx = it*128 + threadIdx.x;
            int pix = idx >> 4;
            int j   = idx & 15;
            g_u[(pbase + pix)*64 + cc*16 + j] = s_tile[pix*17 + j];
        }
        __syncthreads();
    }
}

// ---------------------------------------------------------------------------
// Scan v2: thread = (sequence, channel, half-of-states). Lanes 2d / 2d+1 hold
// states 0..7 / 8..15 of channel d; y reduced with shfl.xor(1). Loads for
// iteration l+1 are issued before computing iteration l (software pipeline).
// Blocks 0..511 horizontal, 512..1023 vertical; 1 sequence per 128-thr block.
// ---------------------------------------------------------------------------
__global__ __launch_bounds__(128) void scan_kernel()
{
    int tid  = threadIdx.x;
    int d    = tid >> 1;          // channel 0..63
    int half = tid & 1;           // state group
    int blk  = blockIdx.x;        // 0..1023
    int dir  = blk >> 9;          // 0 = H, 1 = V
    int s    = blk & 511;
    int b    = s >> 7;
    int rc   = s & 127;           // h for H-scan, w for V-scan

    size_t pix0;
    int stride;
    float* __restrict__ yout;
    if (dir == 0) { pix0 = ((size_t)(b*128 + rc))*128; stride = 1;   yout = g_yh; }
    else          { pix0 = (size_t)b*16384 + rc;       stride = 128; yout = g_yv; }

    float A2r[8];
    #pragma unroll
    for (int n = 0; n < 8; n++) A2r[n] = g_A2[d*16 + half*8 + n];

    float hs[8];
    #pragma unroll
    for (int n = 0; n < 8; n++) hs[n] = 0.f;

    size_t p = pix0;

    // Prologue loads (iteration 0)
    float delta = g_delta[p*64 + d];
    float uu    = g_u[p*64 + d];
    const float4* Bp = (const float4*)(g_Bc + p*16) + half*2;
    const float4* Cp = (const float4*)(g_Cc + p*16) + half*2;
    float4 Bv0 = Bp[0], Bv1 = Bp[1];
    float4 Cv0 = Cp[0], Cv1 = Cp[1];

    for (int l = 0; l < 128; l++) {
        // Prefetch next iteration (clamped on last iter; loads stay in-bounds)
        size_t pn = p + (l < 127 ? stride : 0);
        float delta_n = g_delta[pn*64 + d];
        float uu_n    = g_u[pn*64 + d];
        const float4* Bpn = (const float4*)(g_Bc + pn*16) + half*2;
        const float4* Cpn = (const float4*)(g_Cc + pn*16) + half*2;
        float4 Bn0 = Bpn[0], Bn1 = Bpn[1];
        float4 Cn0 = Cpn[0], Cn1 = Cpn[1];

        float du = delta * uu;
        float y = 0.f;

#define SSM_STEP(n, bv, cv)                                   \
        {                                                     \
            float dA = fexp2(delta * A2r[n]);                 \
            hs[n] = fmaf(dA, hs[n], du * (bv));               \
            y = fmaf(hs[n], (cv), y);                         \
        }
        SSM_STEP(0, Bv0.x, Cv0.x); SSM_STEP(1, Bv0.y, Cv0.y);
        SSM_STEP(2, Bv0.z, Cv0.z); SSM_STEP(3, Bv0.w, Cv0.w);
        SSM_STEP(4, Bv1.x, Cv1.x); SSM_STEP(5, Bv1.y, Cv1.y);
        SSM_STEP(6, Bv1.z, Cv1.z); SSM_STEP(7, Bv1.w, Cv1.w);
#undef SSM_STEP

        // reduce the two halves of this channel (lanes 2d, 2d+1)
        y += __shfl_xor_sync(0xffffffffu, y, 1);
        if (half == 0) yout[p*64 + d] = y;

        delta = delta_n; uu = uu_n;
        Bv0 = Bn0; Bv1 = Bn1; Cv0 = Cn0; Cv1 = Cn1;
        p = pn;
    }
}

// ---------------------------------------------------------------------------
// Combine + transpose: out[b,c,h,w] = yh[p][c] + yv[p][c] + 2*D[c]*x[b,c,h,w]
// 32x32 smem tile per (c-tile, w-tile) so both sides are coalesced.
// ---------------------------------------------------------------------------
__global__ void combine_kernel(const float* __restrict__ x,
                               const float* __restrict__ Dv,
                               float* __restrict__ out)
{
    __shared__ float s[32][33];
    int t    = blockIdx.x;
    int tile = t & 7;          // 2 c-tiles x 4 w-tiles
    int bh   = t >> 3;
    int b    = bh >> 7;
    int h    = bh & 127;
    int c0   = (tile & 1) * 32;
    int w0   = (tile >> 1) * 32;
    int tx   = threadIdx.x;    // 0..31
    int ty   = threadIdx.y;    // 0..7
    size_t pbase = (size_t)bh * 128;

    #pragma unroll
    for (int i = 0; i < 4; i++) {
        int wi = ty + i*8;
        size_t idx = (pbase + w0 + wi)*64 + c0 + tx;
        s[wi][tx] = g_yh[idx] + g_yv[idx];
    }
    __syncthreads();
    #pragma unroll
    for (int i = 0; i < 4; i++) {
        int ci = ty + i*8;
        int c  = c0 + ci;
        size_t xi = (((size_t)(b*64 + c))*128 + h)*128 + w0 + tx;
        out[xi] = s[tx][ci] + 2.f * Dv[c] * x[xi];
    }
}

// ---------------------------------------------------------------------------
extern "C" void kernel_launch(void* const* d_in, const int* in_sizes, int n_in,
                              void* d_out, int out_size)
{
    const float* x     = (const float*)d_in[0];   // [4,64,128,128]
    const float* A_log = (const float*)d_in[1];   // [64,16]
    const float* Dv    = (const float*)d_in[2];   // [64]
    const float* xw    = (const float*)d_in[3];   // [36,64]
    const float* dtw   = (const float*)d_in[4];   // [64,4]
    const float* dtb   = (const float*)d_in[5];   // [64]
    float* out = (float*)d_out;

    setup_kernel<<<24, 256>>>(A_log, xw, dtw);
    proj_kernel<<<NB*NH, 128>>>(x, dtb);
    scan_kernel<<<1024, 128>>>();
    combine_kernel<<<NB*NH*8, dim3(32, 8)>>>(x, Dv, out);
}

// round 3
// speedup vs baseline: 1.3214x; 1.0336x over previous
#include <cuda_runtime.h>
#include <cuda_bf16.h>

// Problem constants
#define NB 4
#define NC 64
#define NH 128
#define NW 128
#define NN 16
#define NPIX (NB*NH*NW)   // 65536 pixels

typedef unsigned long long u64;

// Scratch (allocation-free rule: __device__ globals)
static __device__ float g_W96[96*64];
static __device__ float g_A2[64*16];
static __device__ float g_delta[(size_t)NPIX*64];
static __device__ float g_u[(size_t)NPIX*64];
static __device__ float g_Bc[(size_t)NPIX*16];
static __device__ float g_Cc[(size_t)NPIX*16];
static __device__ float g_yh[(size_t)NPIX*64];
static __device__ float g_yv[(size_t)NPIX*64];

__device__ __forceinline__ float fexp2(float x) {
    float r;
    asm("ex2.approx.f32 %0, %1;" : "=f"(r) : "f"(x));
    return r;
}
__device__ __forceinline__ u64 pack2(float lo, float hi) {
    u64 r; asm("mov.b64 %0, {%1, %2};" : "=l"(r) : "f"(lo), "f"(hi)); return r;
}
__device__ __forceinline__ void unpack2(u64 v, float& lo, float& hi) {
    asm("mov.b64 {%0, %1}, %2;" : "=f"(lo), "=f"(hi) : "l"(v));
}
__device__ __forceinline__ u64 fma2(u64 a, u64 b, u64 c) {
    u64 d; asm("fma.rn.f32x2 %0, %1, %2, %3;" : "=l"(d) : "l"(a), "l"(b), "l"(c)); return d;
}
__device__ __forceinline__ u64 mul2(u64 a, u64 b) {
    u64 d; asm("mul.rn.f32x2 %0, %1, %2;" : "=l"(d) : "l"(a), "l"(b)); return d;
}

// ---------------------------------------------------------------------------
__global__ void setup_kernel(const float* __restrict__ A_log,
                             const float* __restrict__ xw,    // [36,64]
                             const float* __restrict__ dtw)   // [64,4]
{
    int i = blockIdx.x * blockDim.x + threadIdx.x;
    if (i < 96*64) {
        int r = i >> 6, c = i & 63;
        float v;
        if (r < 64) {
            v = dtw[r*4+0]*xw[0*64+c] + dtw[r*4+1]*xw[1*64+c]
              + dtw[r*4+2]*xw[2*64+c] + dtw[r*4+3]*xw[3*64+c];
        } else {
            v = xw[(r - 64 + 4)*64 + c];
        }
        g_W96[i] = v;
    }
    if (i < 64*16) {
        g_A2[i] = -__expf(A_log[i]) * 1.4426950408889634f;
    }
}

// ---------------------------------------------------------------------------
// Projection v3: 256 threads per (b,h) row; two 128-thread groups, each
// computing 48 of the 96 outputs for all 128 pixels with packed f32x2 FMA.
// ---------------------------------------------------------------------------
__global__ __launch_bounds__(256) void proj_kernel(const float* __restrict__ x,
                                                   const float* __restrict__ dtb)
{
    __shared__ __align__(16) float s_w[96*64];      // 24 KB
    __shared__ float s_tile[2][128*17];             // per-group staging
    __shared__ float s_bias[64];

    int bh  = blockIdx.x;          // 0..511
    int b   = bh >> 7;
    int h   = bh & 127;
    int w   = threadIdx.x & 127;   // pixel
    int grp = threadIdx.x >> 7;    // output group

    for (int i = threadIdx.x; i < 96*64; i += 256) s_w[i] = g_W96[i];
    if (threadIdx.x < 64) s_bias[threadIdx.x] = dtb[threadIdx.x];

    float u[64];
    const float* xp = x + ((size_t)(b*64)*128 + h)*128 + w;
    #pragma unroll
    for (int c = 0; c < 64; c++) u[c] = xp[(size_t)c*16384];
    u64 u2[32];
    #pragma unroll
    for (int c = 0; c < 32; c++) u2[c] = pack2(u[2*c], u[2*c+1]);

    __syncthreads();

    size_t pbase = (size_t)bh * 128;

    for (int ch = 0; ch < 3; ch++) {
        int chunk = grp*3 + ch;        // grp0: 0,1,2  grp1: 3,4,5
        int o0 = chunk * 16;
        #pragma unroll 4
        for (int j = 0; j < 16; j++) {
            const ulonglong2* wr = (const ulonglong2*)(s_w + (o0 + j)*64);
            u64 acc2 = 0ull;
            #pragma unroll
            for (int c = 0; c < 16; c++) {
                ulonglong2 wv = wr[c];            // 4 floats = 2 packed pairs
                acc2 = fma2(u2[2*c],   wv.x, acc2);
                acc2 = fma2(u2[2*c+1], wv.y, acc2);
            }
            float lo, hi; unpack2(acc2, lo, hi);
            s_tile[grp][w*17 + j] = lo + hi;
        }
        __syncthreads();
        #pragma unroll
        for (int it = 0; it < 16; it++) {
            int idx = it*128 + w;
            int pix = idx >> 4;
            int j   = idx & 15;
            float v = s_tile[grp][pix*17 + j];
            if (chunk < 4) {
                int o = chunk*16 + j;
                v += s_bias[o];
                v = (v > 15.f) ? v : __logf(1.f + __expf(v));   // softplus
                g_delta[(pbase + pix)*64 + o] = v;
            } else if (chunk == 4) {
                g_Bc[(pbase + pix)*16 + j] = v;
            } else {
                g_Cc[(pbase + pix)*16 + j] = v;
            }
        }
        __syncthreads();
    }

    // u transpose to [p][c]: group g writes channel blocks 2g, 2g+1
    #pragma unroll
    for (int k = 0; k < 2; k++) {
        int cc = grp*2 + k;
        #pragma unroll
        for (int j = 0; j < 16; j++) s_tile[grp][w*17 + j] = u[cc*16 + j];
        __syncthreads();
        #pragma unroll
        for (int it = 0; it < 16; it++) {
            int idx = it*128 + w;
            int pix = idx >> 4;
            int j   = idx & 15;
            g_u[(pbase + pix)*64 + cc*16 + j] = s_tile[grp][pix*17 + j];
        }
        __syncthreads();
    }
}

// ---------------------------------------------------------------------------
// Scan v3: thread = (sequence, channel, half-of-states); packed f32x2 state
// updates, software-pipelined loads, shfl reduction.
// ---------------------------------------------------------------------------
__global__ __launch_bounds__(128) void scan_kernel()
{
    int tid  = threadIdx.x;
    int d    = tid >> 1;          // channel 0..63
    int half = tid & 1;           // state group (0: n=0..7, 1: n=8..15)
    int blk  = blockIdx.x;        // 0..1023
    int dir  = blk >> 9;          // 0 = H, 1 = V
    int s    = blk & 511;
    int b    = s >> 7;
    int rc   = s & 127;

    size_t pix0;
    int stride;
    float* __restrict__ yout;
    if (dir == 0) { pix0 = ((size_t)(b*128 + rc))*128; stride = 1;   yout = g_yh; }
    else          { pix0 = (size_t)b*16384 + rc;       stride = 128; yout = g_yv; }

    u64 A22[4];
    #pragma unroll
    for (int q = 0; q < 4; q++) {
        const float* ap = g_A2 + d*16 + half*8 + 2*q;
        A22[q] = pack2(ap[0], ap[1]);
    }

    u64 hs2[4];
    #pragma unroll
    for (int q = 0; q < 4; q++) hs2[q] = 0ull;

    size_t p = pix0;

    // Prologue loads: this half's 8 states = 32B of B and of C
    float delta = g_delta[p*64 + d];
    float uu    = g_u[p*64 + d];
    ulonglong2 Bv = *(const ulonglong2*)(g_Bc + p*16 + half*8);
    ulonglong2 Cv = *(const ulonglong2*)(g_Cc + p*16 + half*8);
    ulonglong2 Bw = *(const ulonglong2*)(g_Bc + p*16 + half*8 + 4);
    ulonglong2 Cw = *(const ulonglong2*)(g_Cc + p*16 + half*8 + 4);

    for (int l = 0; l < 128; l++) {
        size_t pn = p + (l < 127 ? stride : 0);
        float delta_n = g_delta[pn*64 + d];
        float uu_n    = g_u[pn*64 + d];
        ulonglong2 Bn = *(const ulonglong2*)(g_Bc + pn*16 + half*8);
        ulonglong2 Cn = *(const ulonglong2*)(g_Cc + pn*16 + half*8);
        ulonglong2 Bm = *(const ulonglong2*)(g_Bc + pn*16 + half*8 + 4);
        ulonglong2 Cm = *(const ulonglong2*)(g_Cc + pn*16 + half*8 + 4);

        float du = delta * uu;
        u64 du2 = pack2(du, du);
        u64 delta2 = pack2(delta, delta);
        u64 y2 = 0ull;

#define SSM_STEP2(q, bv, cv)                                       \
        {                                                          \
            u64 e2 = mul2(delta2, A22[q]);                         \
            float e0, e1; unpack2(e2, e0, e1);                     \
            u64 dA2 = pack2(fexp2(e0), fexp2(e1));                 \
            hs2[q] = fma2(dA2, hs2[q], mul2(du2, (bv)));           \
            y2 = fma2(hs2[q], (cv), y2);                           \
        }
        SSM_STEP2(0, Bv.x, Cv.x);
        SSM_STEP2(1, Bv.y, Cv.y);
        SSM_STEP2(2, Bw.x, Cw.x);
        SSM_STEP2(3, Bw.y, Cw.y);
#undef SSM_STEP2

        float ylo, yhi; unpack2(y2, ylo, yhi);
        float y = ylo + yhi;
        y += __shfl_xor_sync(0xffffffffu, y, 1);
        if (half == 0) yout[p*64 + d] = y;

        delta = delta_n; uu = uu_n;
        Bv = Bn; Bw = Bm; Cv = Cn; Cw = Cm;
        p = pn;
    }
}

// ---------------------------------------------------------------------------
__global__ void combine_kernel(const float* __restrict__ x,
                               const float* __restrict__ Dv,
                               float* __restrict__ out)
{
    __shared__ float s[32][33];
    int t    = blockIdx.x;
    int tile = t & 7;
    int bh   = t >> 3;
    int b    = bh >> 7;
    int h    = bh & 127;
    int c0   = (tile & 1) * 32;
    int w0   = (tile >> 1) * 32;
    int tx   = threadIdx.x;
    int ty   = threadIdx.y;
    size_t pbase = (size_t)bh * 128;

    #pragma unroll
    for (int i = 0; i < 4; i++) {
        int wi = ty + i*8;
        size_t idx = (pbase + w0 + wi)*64 + c0 + tx;
        s[wi][tx] = g_yh[idx] + g_yv[idx];
    }
    __syncthreads();
    #pragma unroll
    for (int i = 0; i < 4; i++) {
        int ci = ty + i*8;
        int c  = c0 + ci;
        size_t xi = (((size_t)(b*64 + c))*128 + h)*128 + w0 + tx;
        out[xi] = s[tx][ci] + 2.f * Dv[c] * x[xi];
    }
}

// ---------------------------------------------------------------------------
extern "C" void kernel_launch(void* const* d_in, const int* in_sizes, int n_in,
                              void* d_out, int out_size)
{
    const float* x     = (const float*)d_in[0];
    const float* A_log = (const float*)d_in[1];
    const float* Dv    = (const float*)d_in[2];
    const float* xw    = (const float*)d_in[3];
    const float* dtw   = (const float*)d_in[4];
    const float* dtb   = (const float*)d_in[5];
    float* out = (float*)d_out;

    setup_kernel<<<24, 256>>>(A_log, xw, dtw);
    proj_kernel<<<NB*NH, 256>>>(x, dtb);
    scan_kernel<<<1024, 128>>>();
    combine_kernel<<<NB*NH*8, dim3(32, 8)>>>(x, Dv, out);
}